// round 1
// baseline (speedup 1.0000x reference)
#include <cuda_runtime.h>
#include <cstdint>
#include <cstddef>

// LSTM cell fused as a single GEMM + epilogue.
// C[B, 4H] = [incoming | old_h] @ [Wi | Wh]^T, with N interleaved as n = h*4 + g
// so each output tile holds all 4 gates of its h values -> epilogue fuses in-register.

#define BM 128
#define BN 64
#define BK 32
#define THREADS 256
#define LDA 36  // BK + 4 pad: stride mod 32 == 4 -> conflict-free fragment loads
#define LDB 36

#define MDIM 16384
#define NDIM 4096
#define KDIM 2048
#define HDIM 1024

__device__ __forceinline__ unsigned cvta_s(const void* p) {
    return (unsigned)__cvta_generic_to_shared(p);
}
__device__ __forceinline__ void cp_async16(unsigned s, const void* g) {
    asm volatile("cp.async.cg.shared.global [%0], [%1], 16;\n" :: "r"(s), "l"(g));
}
__device__ __forceinline__ void cp_commit() { asm volatile("cp.async.commit_group;\n" ::: "memory"); }
__device__ __forceinline__ void cp_wait0()  { asm volatile("cp.async.wait_group 0;\n" ::: "memory"); }

__device__ __forceinline__ unsigned f2tf32(float x) {
    unsigned r; asm("cvt.rna.tf32.f32 %0, %1;\n" : "=r"(r) : "f"(x)); return r;
}

__device__ __forceinline__ void mma_tf32(float* d, const unsigned* a, const unsigned* b) {
    asm volatile("mma.sync.aligned.m16n8k8.row.col.f32.tf32.tf32.f32 "
        "{%0,%1,%2,%3}, {%4,%5,%6,%7}, {%8,%9}, {%0,%1,%2,%3};\n"
        : "+f"(d[0]), "+f"(d[1]), "+f"(d[2]), "+f"(d[3])
        : "r"(a[0]), "r"(a[1]), "r"(a[2]), "r"(a[3]), "r"(b[0]), "r"(b[1]));
}

__device__ __forceinline__ void load_stage(
    float* As, float* Bs, int s,
    const float* __restrict__ aptr, const float* __restrict__ bptr, int koff,
    int bm, int bn, int tid)
{
    int row0 = tid >> 3;          // 0..31
    int ck   = (tid & 7) << 2;    // 0,4,...,28
#pragma unroll
    for (int i = 0; i < 4; i++) {
        int r = row0 + i * 32;
        const float* g = aptr + (size_t)(bm + r) * 1024 + koff + ck;
        cp_async16(cvta_s(&As[(size_t)(s * BM + r) * LDA + ck]), g);
    }
#pragma unroll
    for (int i = 0; i < 2; i++) {
        int r = row0 + i * 32;
        int n = bn + r;
        // weight row for output column n: gate g = n&3, unit h = n>>2
        const float* g = bptr + (size_t)((n & 3) * HDIM + (n >> 2)) * 1024 + koff + ck;
        cp_async16(cvta_s(&Bs[(size_t)(s * BN + r) * LDB + ck]), g);
    }
    cp_commit();
}

__global__ void __launch_bounds__(THREADS, 2)
lstm_cell_kernel(const float* __restrict__ incoming,
                 const float* __restrict__ old_h,
                 const float* __restrict__ old_c,
                 const float* __restrict__ Wi,
                 const float* __restrict__ bi,
                 const float* __restrict__ Wh,
                 float* __restrict__ out, long long out_size)
{
    extern __shared__ float smem[];
    float* As = smem;                      // [2][BM][LDA]
    float* Bs = smem + 2 * BM * LDA;       // [2][BN][LDB]

    const int tid  = threadIdx.x;
    const int lane = tid & 31;
    const int warp = tid >> 5;
    const int wr = warp >> 1;   // 0..3 (M)
    const int wc = warp & 1;    // 0..1 (N)
    const int bm = blockIdx.y * BM;
    const int bn = blockIdx.x * BN;

    const int gid = lane >> 2;  // 0..7
    const int q   = lane & 3;   // 0..3

    float acc[2][4][4];
#pragma unroll
    for (int a = 0; a < 2; a++)
#pragma unroll
        for (int b = 0; b < 4; b++)
#pragma unroll
            for (int c = 0; c < 4; c++) acc[a][b][c] = 0.f;

    const int NKT = KDIM / BK;  // 64

    // prologue: stage 0 = ktile 0 (k0 = 0 < 1024 -> incoming/Wi)
    load_stage(As, Bs, 0, incoming, Wi, 0, bm, bn, tid);

    for (int kt = 0; kt < NKT; kt++) {
        cp_wait0();
        __syncthreads();

        if (kt + 1 < NKT) {
            int k0 = (kt + 1) * BK;
            const float* ap = (k0 < 1024) ? incoming : old_h;
            const float* bp = (k0 < 1024) ? Wi : Wh;
            int koff = (k0 < 1024) ? k0 : (k0 - 1024);
            load_stage(As, Bs, (kt + 1) & 1, ap, bp, koff, bm, bn, tid);
        }

        const float* A0 = &As[(size_t)((kt & 1) * BM) * LDA];
        const float* B0 = &Bs[(size_t)((kt & 1) * BN) * LDB];

#pragma unroll
        for (int ks = 0; ks < 4; ks++) {
            int k8 = ks * 8;
            unsigned afr[2][4], bfr[4][2];
#pragma unroll
            for (int mt = 0; mt < 2; mt++) {
                int rb = wr * 32 + mt * 16;
                afr[mt][0] = f2tf32(A0[(rb + gid    ) * LDA + k8 + q    ]);
                afr[mt][1] = f2tf32(A0[(rb + gid + 8) * LDA + k8 + q    ]);
                afr[mt][2] = f2tf32(A0[(rb + gid    ) * LDA + k8 + q + 4]);
                afr[mt][3] = f2tf32(A0[(rb + gid + 8) * LDA + k8 + q + 4]);
            }
#pragma unroll
            for (int nt = 0; nt < 4; nt++) {
                int nb = wc * 32 + nt * 8;
                bfr[nt][0] = f2tf32(B0[(nb + gid) * LDB + k8 + q    ]);
                bfr[nt][1] = f2tf32(B0[(nb + gid) * LDB + k8 + q + 4]);
            }
#pragma unroll
            for (int mt = 0; mt < 2; mt++)
#pragma unroll
                for (int nt = 0; nt < 4; nt++)
                    mma_tf32(acc[mt][nt], afr[mt], bfr[nt]);
        }
        __syncthreads();
    }

    // ---- fused LSTM epilogue ----
    // accumulator (mt,nt) regs: [0]=(row gid, col 2q) [1]=(row gid, col 2q+1)
    //                           [2]=(row gid+8, col 2q) [3]=(row gid+8, col 2q+1)
    // col n = bn + wc*32 + nt*8 + 2q (+1). gate = n&3, unit h = n>>2.
    // lanes q and q^1 share h: even-q lane holds (i_pre, f_pre), odd-q lane (g_pre, o_pre).
    const long long BH = (long long)MDIM * HDIM;
    const bool seg1 = out_size >= 2 * BH;
    const bool seg2 = out_size >= 3 * BH;

#pragma unroll
    for (int mt = 0; mt < 2; mt++) {
#pragma unroll
        for (int rr = 0; rr < 2; rr++) {
            int b = bm + wr * 32 + mt * 16 + gid + rr * 8;
#pragma unroll
            for (int nt = 0; nt < 4; nt++) {
                int n = bn + wc * 32 + nt * 8 + 2 * q;  // even column of the pair
                int g0 = n & 3;      // 0 (even q) or 2 (odd q)
                int h  = n >> 2;
                float v0 = acc[mt][nt][rr * 2 + 0] + bi[g0 * HDIM + h];
                float v1 = acc[mt][nt][rr * 2 + 1] + bi[(g0 + 1) * HDIM + h];
                float p0 = __shfl_xor_sync(0xffffffffu, v0, 1);
                float p1 = __shfl_xor_sync(0xffffffffu, v1, 1);
                float ipre, fpre, gpre, opre;
                if ((q & 1) == 0) { ipre = v0; fpre = v1; gpre = p0; opre = p1; }
                else              { ipre = p0; fpre = p1; gpre = v0; opre = v1; }

                float iv = 1.f / (1.f + __expf(-ipre));
                float fv = 1.f / (1.f + __expf(-fpre));
                float gv = tanhf(gpre);
                float ov = 1.f / (1.f + __expf(-opre));

                float oc = old_c[(size_t)b * HDIM + h];
                float nc = fv * oc + iv * gv;
                float nh = ov * tanhf(nc);

                size_t idx = (size_t)b * HDIM + h;
                if ((q & 1) == 0) {
                    out[idx] = nh;                       // leaf 0: new_h
                } else {
                    if (seg1) out[(size_t)BH + idx] = nh;        // leaf 1: new_h
                    if (seg2) out[(size_t)(2 * BH) + idx] = nc;  // leaf 2: new_c
                }
            }
        }
    }
}

extern "C" void kernel_launch(void* const* d_in, const int* in_sizes, int n_in,
                              void* d_out, int out_size) {
    const float* incoming = (const float*)d_in[0];
    const float* old_h    = (const float*)d_in[1];
    const float* old_c    = (const float*)d_in[2];
    const float* Wi       = (const float*)d_in[3];
    const float* bi       = (const float*)d_in[4];
    const float* Wh       = (const float*)d_in[5];
    float* out = (float*)d_out;

    size_t smem_bytes = (size_t)(2 * BM * LDA + 2 * BN * LDB) * sizeof(float); // 55296
    cudaFuncSetAttribute(lstm_cell_kernel,
                         cudaFuncAttributeMaxDynamicSharedMemorySize, (int)smem_bytes);

    dim3 grid(NDIM / BN, MDIM / BM);  // (64, 128)
    lstm_cell_kernel<<<grid, THREADS, smem_bytes>>>(
        incoming, old_h, old_c, Wi, bi, Wh, out, (long long)out_size);
}

// round 3
// speedup vs baseline: 2.1113x; 2.1113x over previous
#include <cuda_runtime.h>
#include <cuda_fp16.h>
#include <cstdint>
#include <cstddef>

#define MDIM 16384
#define NDIM 4096
#define KDIM 2048
#define HDIM 1024

#define BM 256
#define BN 128
#define BK 32
#define STAGES 4
#define THREADS 512
#define NKT (KDIM / BK)              // 64

#define A_BYTES 16384                // BM/16 * BK/16 * 512
#define B_BYTES 8192                 // BN/8  * BK/32 * 512
#define STAGE_BYTES (A_BYTES + B_BYTES)   // 24576

// Fragment-packed operands (device globals: allowed scratch)
__device__ __half g_Apack[(size_t)MDIM * KDIM];   // 64 MB
__device__ __half g_Wpack[(size_t)NDIM * KDIM];   // 16 MB

// ---------------- helpers ----------------
__device__ __forceinline__ uint32_t cvta_s(const void* p) {
    return (uint32_t)__cvta_generic_to_shared(p);
}
__device__ __forceinline__ void cp_async16(uint32_t s, const void* g) {
    asm volatile("cp.async.cg.shared.global [%0], [%1], 16;\n" :: "r"(s), "l"(g));
}
__device__ __forceinline__ void cp_commit() { asm volatile("cp.async.commit_group;\n" ::: "memory"); }
#define CP_WAIT(n) asm volatile("cp.async.wait_group %0;\n" :: "n"(n) : "memory")

__device__ __forceinline__ void mma_f16(float* d, const uint32_t* a, const uint32_t* b) {
    asm volatile("mma.sync.aligned.m16n8k16.row.col.f32.f16.f16.f32 "
        "{%0,%1,%2,%3}, {%4,%5,%6,%7}, {%8,%9}, {%0,%1,%2,%3};\n"
        : "+f"(d[0]), "+f"(d[1]), "+f"(d[2]), "+f"(d[3])
        : "r"(a[0]), "r"(a[1]), "r"(a[2]), "r"(a[3]), "r"(b[0]), "r"(b[1]));
}

// ---------------- pack kernels ----------------
// A fragment unit: m16 x k16 tile -> 32 lanes x 8 halves (16B), lane (gid=l>>2,q=l&3):
//   j0,j1=(gid,2q..)  j2,j3=(gid+8,2q..)  j4,j5=(gid,2q+8..)  j6,j7=(gid+8,2q+8..)
__global__ void pack_A(const float* __restrict__ inc, const float* __restrict__ oh) {
    int idx = blockIdx.x * blockDim.x + threadIdx.x;     // one 16B chunk
    int lane = idx & 31;
    int unit = idx >> 5;
    int kblk = unit & 127;        // K/16
    int mblk = unit >> 7;
    int gid = lane >> 2, q = lane & 3;
    int m0 = mblk * 16 + gid;
    int k0 = kblk * 16 + 2 * q;
    const float* src;
    if (k0 < 1024) src = inc + (size_t)m0 * 1024 + k0;
    else           src = oh  + (size_t)m0 * 1024 + (k0 - 1024);
    float2 v0 = *(const float2*)(src);
    float2 v1 = *(const float2*)(src + 8 * 1024);
    float2 v2 = *(const float2*)(src + 8);
    float2 v3 = *(const float2*)(src + 8 * 1024 + 8);
    __half2 h[4];
    h[0] = __floats2half2_rn(v0.x, v0.y);
    h[1] = __floats2half2_rn(v1.x, v1.y);
    h[2] = __floats2half2_rn(v2.x, v2.y);
    h[3] = __floats2half2_rn(v3.x, v3.y);
    *(float4*)(g_Apack + (size_t)unit * 256 + lane * 8) = *(float4*)h;
}

// B fragment unit: n8 x k32 tile -> 32 lanes x 8 halves. Output col n = nblk*8+gid,
// gate-interleaved: n = 4h+g, source row = g*1024+h of [Wi|Wh].
//   j0,j1=(k=2q,2q+1)  j2,j3=(k=2q+8,2q+9)  j4..j7 = same +16
__global__ void pack_W(const float* __restrict__ Wi, const float* __restrict__ Wh) {
    int idx = blockIdx.x * blockDim.x + threadIdx.x;
    int lane = idx & 31;
    int unit = idx >> 5;
    int kblk = unit & 63;         // K/32
    int nblk = unit >> 6;
    int gid = lane >> 2, q = lane & 3;
    int n = nblk * 8 + gid;
    int g = n & 3, hh = n >> 2;
    int k0 = kblk * 32 + 2 * q;
    const float* src;
    if (k0 < 1024) src = Wi + ((size_t)g * 1024 + hh) * 1024 + k0;
    else           src = Wh + ((size_t)g * 1024 + hh) * 1024 + (k0 - 1024);
    float2 v0 = *(const float2*)(src);
    float2 v1 = *(const float2*)(src + 8);
    float2 v2 = *(const float2*)(src + 16);
    float2 v3 = *(const float2*)(src + 24);
    __half2 h[4];
    h[0] = __floats2half2_rn(v0.x, v0.y);
    h[1] = __floats2half2_rn(v1.x, v1.y);
    h[2] = __floats2half2_rn(v2.x, v2.y);
    h[3] = __floats2half2_rn(v3.x, v3.y);
    *(float4*)(g_Wpack + (size_t)unit * 256 + lane * 8) = *(float4*)h;
}

// ---------------- main GEMM + fused LSTM epilogue ----------------
__global__ void __launch_bounds__(THREADS, 1)
lstm_mma(const float* __restrict__ old_c, const float* __restrict__ bi,
         float* __restrict__ out, long long out_size)
{
    extern __shared__ char dsm[];
    __shared__ float s_bias[BN];

    const int tid  = threadIdx.x;
    const int lane = tid & 31;
    const int warp = tid >> 5;            // 0..15
    const int wr = warp >> 2;             // 0..3 -> M (64 rows each)
    const int wc = warp & 3;              // 0..3 -> N (32 cols each)
    const int bm = blockIdx.y * BM;
    const int bn = blockIdx.x * BN;
    const int gid = lane >> 2, q = lane & 3;

    const uint32_t smem = cvta_s(dsm);

    float acc[4][4][4];
#pragma unroll
    for (int a = 0; a < 4; a++)
#pragma unroll
        for (int b = 0; b < 4; b++)
#pragma unroll
            for (int c = 0; c < 4; c++) acc[a][b][c] = 0.f;

    // per-thread producer roles
    const int mblk = tid >> 5;            // 0..15 (A row-block, also B n-block)
    const __half* Ag0 = g_Apack + ((size_t)(bm / 16 + mblk) * 128) * 256 + lane * 8;
    const __half* Bg0 = g_Wpack + ((size_t)(bn / 8 + mblk) * 64) * 256 + lane * 8;

    auto produce = [&](int kt, int st) {
        uint32_t sa = smem + st * STAGE_BYTES;
        uint32_t sb = sa + A_BYTES;
        const __half* Ag = Ag0 + (size_t)(kt * 2) * 256;
        cp_async16(sa + (mblk * 2 + 0) * 512 + lane * 16, Ag);
        cp_async16(sa + (mblk * 2 + 1) * 512 + lane * 16, Ag + 256);
        cp_async16(sb + mblk * 512 + lane * 16, Bg0 + (size_t)kt * 256);
    };

    // prologue: stages 0..2
#pragma unroll
    for (int s = 0; s < STAGES - 1; s++) {
        produce(s, s);
        cp_commit();
    }

    for (int kt = 0; kt < NKT; kt++) {
        CP_WAIT(STAGES - 2);          // group kt complete
        __syncthreads();              // all warps done reading stage (kt-1)%4

        int nk = kt + STAGES - 1;
        if (nk < NKT) produce(nk, nk & (STAGES - 1));
        cp_commit();                  // always commit (empty ok) -> wait math stays fixed

        const char* sA = dsm + (kt & (STAGES - 1)) * STAGE_BYTES;
        const char* sB = sA + A_BYTES;

        uint32_t bfr[4][4];
#pragma unroll
        for (int nt = 0; nt < 4; nt++)
            *(uint4*)bfr[nt] = *(const uint4*)(sB + (wc * 4 + nt) * 512 + lane * 16);

#pragma unroll
        for (int ks = 0; ks < 2; ks++) {
            uint32_t afr[4][4];
#pragma unroll
            for (int mt = 0; mt < 4; mt++)
                *(uint4*)afr[mt] = *(const uint4*)(sA + ((wr * 4 + mt) * 2 + ks) * 512 + lane * 16);
#pragma unroll
            for (int mt = 0; mt < 4; mt++)
#pragma unroll
                for (int nt = 0; nt < 4; nt++)
                    mma_f16(acc[mt][nt], afr[mt], &bfr[nt][ks * 2]);
        }
    }

    // stage bias for this CTA's 128 columns (gate-interleaved source)
    __syncthreads();
    if (tid < BN) {
        int n = bn + tid;
        s_bias[tid] = bi[(n & 3) * HDIM + (n >> 2)];
    }
    __syncthreads();

    // ---- fused LSTM epilogue (round-1 verified pairing) ----
    // acc regs: [0]=(row gid, col 2q) [1]=(row gid, col 2q+1) [2]=(+8, 2q) [3]=(+8, 2q+1)
    // even-q lane holds (i,f) pre-acts, odd-q lane (g,o) of the SAME h -> shfl.xor 1
    const long long BH = (long long)MDIM * HDIM;
    const bool seg1 = out_size >= 2 * BH;
    const bool seg2 = out_size >= 3 * BH;

#pragma unroll
    for (int mt = 0; mt < 4; mt++) {
#pragma unroll
        for (int rr = 0; rr < 2; rr++) {
            int b = bm + wr * 64 + mt * 16 + gid + rr * 8;
#pragma unroll
            for (int nt = 0; nt < 4; nt++) {
                int cn = wc * 32 + nt * 8 + 2 * q;   // local even col
                int n  = bn + cn;
                int h  = n >> 2;
                float v0 = acc[mt][nt][rr * 2 + 0] + s_bias[cn];
                float v1 = acc[mt][nt][rr * 2 + 1] + s_bias[cn + 1];
                float p0 = __shfl_xor_sync(0xffffffffu, v0, 1);
                float p1 = __shfl_xor_sync(0xffffffffu, v1, 1);
                float ipre, fpre, gpre, opre;
                if ((q & 1) == 0) { ipre = v0; fpre = v1; gpre = p0; opre = p1; }
                else              { ipre = p0; fpre = p1; gpre = v0; opre = v1; }

                float iv = 1.f / (1.f + __expf(-ipre));
                float fv = 1.f / (1.f + __expf(-fpre));
                float gv = 2.f / (1.f + __expf(-2.f * gpre)) - 1.f;
                float ov = 1.f / (1.f + __expf(-opre));

                float oc = old_c[(size_t)b * HDIM + h];
                float nc = fv * oc + iv * gv;
                float nh = ov * (2.f / (1.f + __expf(-2.f * nc)) - 1.f);

                size_t idx = (size_t)b * HDIM + h;
                if ((q & 1) == 0) {
                    out[idx] = nh;
                } else {
                    if (seg1) out[(size_t)BH + idx] = nh;
                    if (seg2) out[(size_t)(2 * BH) + idx] = nc;
                }
            }
        }
    }
}

extern "C" void kernel_launch(void* const* d_in, const int* in_sizes, int n_in,
                              void* d_out, int out_size) {
    const float* incoming = (const float*)d_in[0];
    const float* old_h    = (const float*)d_in[1];
    const float* old_c    = (const float*)d_in[2];
    const float* Wi       = (const float*)d_in[3];
    const float* bi       = (const float*)d_in[4];
    const float* Wh       = (const float*)d_in[5];
    float* out = (float*)d_out;

    // pack: one thread per 16B fragment chunk
    int a_chunks = (MDIM / 16) * (KDIM / 16) * 32;   // 4,194,304
    int w_chunks = (NDIM / 8) * (KDIM / 32) * 32;    // 1,048,576
    pack_A<<<a_chunks / 256, 256>>>(incoming, old_h);
    pack_W<<<w_chunks / 256, 256>>>(Wi, Wh);

    static int smem_set = 0;
    if (!smem_set) {
        cudaFuncSetAttribute(lstm_mma, cudaFuncAttributeMaxDynamicSharedMemorySize,
                             STAGES * STAGE_BYTES);
        smem_set = 1;
    }
    dim3 grid(NDIM / BN, MDIM / BM);   // (32, 64)
    lstm_mma<<<grid, THREADS, STAGES * STAGE_BYTES>>>(old_c, bi, out, (long long)out_size);
}